// round 3
// baseline (speedup 1.0000x reference)
#include <cuda_runtime.h>

// FlowNetC correlation, specialized: B=4, C=128, H=W=96, PAD=20, K=1, MD=20, S1=1, S2=2
// out[b, iy*21+ix, y, x] = (1/128) * sum_c in1[b,c,y,x] * in2[b,c,y+dy,x+dx]
//   dy = (iy-10)*2, dx = (ix-10)*2, zero outside bounds.
//
// Layout: smem rows padded to 132 floats (33 float4 granules). Granule index of
// chunk cb at row r is r*33+cb = r+cb (mod 8)  -> conflict-free without XOR
// swizzle, and compute addresses are affine in the t loop (imm offsets).

#define HW_ 9216            // 96*96 plane stride in floats
#define RS  132             // padded row stride (floats)
#define S1F (96*RS)         // 12672
#define S2ROWS 136          // x in [-20,115] -> row = x+20
#define S2F (S2ROWS*RS)     // 17952
#define SMEM_FLOATS (S1F + 2*S2F)
#define SMEM_BYTES  (SMEM_FLOATS*4)   // 194,304 B

__global__ __launch_bounds__(384, 1)
void corr_kernel(const float* __restrict__ in1, const float* __restrict__ in2,
                 float* __restrict__ out)
{
    extern __shared__ float smem[];
    float* s1 = smem;

    const int tid  = threadIdx.x;
    const int team = tid / 192;          // two dy's per block
    const int t192 = tid - team * 192;
    const int y  = blockIdx.x;           // 0..95
    const int zp = blockIdx.y;           // 0..10
    const int b  = blockIdx.z;           // 0..3

    const int  dyIdx     = zp + team * 11;          // 0..21 (21 = idle)
    const bool teamValid = (dyIdx < 21);
    const int  y2        = y + (dyIdx - 10) * 2;
    const bool rowValid  = teamValid && ((unsigned)y2 < 96u);

    float* s2 = smem + S1F + team * S2F;

    // ---- stage in1 row y: smem layout [x][c], row stride RS ----
    {
        const float* g1 = in1 + ((size_t)b * 128 * 96 + y) * 96;   // + ch*4*HW + x
        for (int i = tid; i < 96 * 32; i += 384) {
            int x = i % 96, ch = i / 96;                           // ch = float4 chunk 0..31
            const float* g = g1 + ch * 4 * HW_ + x;
            float4 v = make_float4(g[0], g[HW_], g[2 * HW_], g[3 * HW_]);
            *(float4*)&s1[x * RS + ch * 4] = v;
        }
    }

    // ---- stage in2 row y2 (per team), zero halo rows x in [-20,-1],[96,115] ----
    if (rowValid) {
        for (int i = t192; i < 40 * 32; i += 192) {
            int r = i % 40, ch = i / 40;
            int row = (r < 20) ? r : (96 + r);                     // rows 0..19, 116..135
            *(float4*)&s2[row * RS + ch * 4] = make_float4(0.f, 0.f, 0.f, 0.f);
        }
        const float* g2 = in2 + ((size_t)b * 128 * 96 + y2) * 96;
        for (int i = t192; i < 96 * 32; i += 192) {
            int x = i % 96, ch = i / 96;
            const float* g = g2 + ch * 4 * HW_ + x;
            float4 v = make_float4(g[0], g[HW_], g[2 * HW_], g[3 * HW_]);
            *(float4*)&s2[(x + 20) * RS + ch * 4] = v;
        }
    }
    __syncthreads();

    if (!teamValid) return;

    const int cg = t192 & 7;                 // channel-group lane (4 ch each; reduced via shfl)
    const int xs = t192 >> 3;                // 0..23
    const int x0 = 8 * (xs >> 1) + (xs & 1); // outputs x0+2*xi, xi=0..3, tile 0..95

    const size_t obase = ((size_t)(b * 441 + dyIdx * 21) * 96 + y) * 96;

    if (rowValid) {
        float acc[4][21];
        #pragma unroll
        for (int xi = 0; xi < 4; xi++)
            #pragma unroll
            for (int j = 0; j < 21; j++) acc[xi][j] = 0.f;

        #pragma unroll 1
        for (int k = 0; k < 4; k++) {
            const int cb = k * 8 + cg;       // this thread's float4 chunk (4 channels)
            const float* s1b = &s1[x0 * RS + cb * 4];
            const float* s2b = &s2[x0 * RS + cb * 4];
            float4 a[4];
            #pragma unroll
            for (int xi = 0; xi < 4; xi++)
                a[xi] = *(const float4*)(s1b + 2 * xi * RS);

            // sliding window: s2 row x0+2t feeds acc[xi][t-xi] for xi=0..3
            #pragma unroll
            for (int t = 0; t < 24; t++) {
                const float4 bv = *(const float4*)(s2b + 2 * t * RS);
                #pragma unroll
                for (int xi = 0; xi < 4; xi++) {
                    const int j = t - xi;
                    if (j >= 0 && j < 21) {
                        float s = acc[xi][j];
                        s = fmaf(a[xi].x, bv.x, s);
                        s = fmaf(a[xi].y, bv.y, s);
                        s = fmaf(a[xi].z, bv.z, s);
                        s = fmaf(a[xi].w, bv.w, s);
                        acc[xi][j] = s;
                    }
                }
            }
        }

        // butterfly-reduce over the 8 channel-group lanes; all lanes end with full sums
        #pragma unroll
        for (int xi = 0; xi < 4; xi++)
            #pragma unroll
            for (int j = 0; j < 21; j++) {
                float v = acc[xi][j];
                v += __shfl_xor_sync(0xffffffffu, v, 1);
                v += __shfl_xor_sync(0xffffffffu, v, 2);
                v += __shfl_xor_sync(0xffffffffu, v, 4);
                acc[xi][j] = v;
            }

        // lane cg stores xi = cg&3, j parity = cg>>2
        const float inv  = 1.0f / 128.0f;
        const int   myxi = cg & 3;
        const int   half = cg >> 2;
        float* o = out + obase + x0 + 2 * myxi;
        #pragma unroll
        for (int j = 0; j < 21; j++) {
            if ((j & 1) == half)
                o[(size_t)j * HW_] = acc[myxi][j] * inv;
        }
    } else {
        // y2 out of range: this dy slab for row y is all zeros
        for (int i = t192; i < 21 * 96; i += 192) {
            int j = i / 96, x = i - j * 96;
            out[obase + (size_t)j * HW_ + x] = 0.f;
        }
    }
}

extern "C" void kernel_launch(void* const* d_in, const int* in_sizes, int n_in,
                              void* d_out, int out_size)
{
    const float* in1 = (const float*)d_in[0];
    const float* in2 = (const float*)d_in[1];
    float* out = (float*)d_out;

    cudaFuncSetAttribute(corr_kernel, cudaFuncAttributeMaxDynamicSharedMemorySize, SMEM_BYTES);

    dim3 grid(96, 11, 4);   // y, dy-pair, batch
    corr_kernel<<<grid, 384, SMEM_BYTES>>>(in1, in2, out);
}

// round 6
// speedup vs baseline: 1.2402x; 1.2402x over previous
#include <cuda_runtime.h>

// FlowNetC correlation, specialized: B=4, C=128, H=W=96, PAD=20, K=1, MD=20, S1=1, S2=2
// out[b, iy*21+ix, y, x] = (1/128) * sum_c in1[b,c,y,x] * in2[b,c,y+dy,x+dx]
//   dy = (iy-10)*2, dx = (ix-10)*2, zero outside bounds.
//
// smem rows padded to 132 floats -> conflict-free (granule = row + chunk mod 8)
// and affine addressing. Inner product uses packed fma.rn.f32x2 (FFMA2) on
// channel pairs loaded directly as ulonglong2 (no packing movs). j-range split
// into two halves to keep packed accumulators at 44 scalars (avoid R3 spill).

#define HW_ 9216            // 96*96 plane stride in floats
#define RS  132             // padded row stride (floats)
#define S1F (96*RS)
#define S2ROWS 136          // x in [-20,115] -> row = x+20
#define S2F (S2ROWS*RS)
#define SMEM_FLOATS (S1F + 2*S2F)
#define SMEM_BYTES  (SMEM_FLOATS*4)   // 194,304 B

typedef unsigned long long ull;

__device__ __forceinline__ ull ffma2(ull a, ull b, ull c) {
    ull d;
    asm("fma.rn.f32x2 %0, %1, %2, %3;" : "=l"(d) : "l"(a), "l"(b), "l"(c));
    return d;
}
__device__ __forceinline__ float2 unpack2(ull v) {
    float2 r;
    asm("mov.b64 {%0, %1}, %2;" : "=f"(r.x), "=f"(r.y) : "l"(v));
    return r;
}

// Compute j in [JLO, JLO+NJ) for output columns x0 and x0+2, reduce over the
// 4 channel-group lanes, store. cg==0 lane stores x0 column, cg==1 stores x0+2.
template<int JLO, int NJ>
__device__ __forceinline__ void compute_half(
    const float* __restrict__ s1, const float* __restrict__ s2,
    int x0, int cg, float* __restrict__ out, size_t obase)
{
    ull acc0[NJ], acc1[NJ];
    #pragma unroll
    for (int j = 0; j < NJ; j++) { acc0[j] = 0ull; acc1[j] = 0ull; }

    #pragma unroll 1
    for (int k = 0; k < 4; k++) {
        const int cb = k * 8 + cg * 2;           // two float4 chunks: cb, cb+1 (8 ch)
        const float* p1 = &s1[x0 * RS + cb * 4];
        const ulonglong2 a0  = *(const ulonglong2*)(p1);
        const ulonglong2 a0b = *(const ulonglong2*)(p1 + 4);
        const ulonglong2 a1  = *(const ulonglong2*)(p1 + 2 * RS);
        const ulonglong2 a1b = *(const ulonglong2*)(p1 + 2 * RS + 4);

        const float* p2 = &s2[(x0 + 2 * JLO) * RS + cb * 4];
        // global t = JLO + t; s2 row = x0 + 2*(JLO+t).
        // acc0[t] needs local t < NJ ; acc1[t-1] needs local t > 0.
        #pragma unroll
        for (int t = 0; t <= NJ; t++) {
            const ulonglong2 b0 = *(const ulonglong2*)(p2 + 2 * t * RS);
            const ulonglong2 b1 = *(const ulonglong2*)(p2 + 2 * t * RS + 4);
            if (t < NJ) {
                ull s = acc0[t];
                s = ffma2(a0.x,  b0.x, s);
                s = ffma2(a0.y,  b0.y, s);
                s = ffma2(a0b.x, b1.x, s);
                s = ffma2(a0b.y, b1.y, s);
                acc0[t] = s;
            }
            if (t > 0) {
                ull s = acc1[t - 1];
                s = ffma2(a1.x,  b0.x, s);
                s = ffma2(a1.y,  b0.y, s);
                s = ffma2(a1b.x, b1.x, s);
                s = ffma2(a1b.y, b1.y, s);
                acc1[t - 1] = s;
            }
        }
    }

    const float inv = 1.0f / 128.0f;
    #pragma unroll
    for (int j = 0; j < NJ; j++) {
        float2 u = unpack2(acc0[j]);
        float v0 = u.x + u.y;
        v0 += __shfl_xor_sync(0xffffffffu, v0, 1);
        v0 += __shfl_xor_sync(0xffffffffu, v0, 2);
        float2 w = unpack2(acc1[j]);
        float v1 = w.x + w.y;
        v1 += __shfl_xor_sync(0xffffffffu, v1, 1);
        v1 += __shfl_xor_sync(0xffffffffu, v1, 2);
        if (cg == 0)
            out[obase + (size_t)(JLO + j) * HW_ + x0] = v0 * inv;
        else if (cg == 1)
            out[obase + (size_t)(JLO + j) * HW_ + x0 + 2] = v1 * inv;
    }
}

__global__ __launch_bounds__(384, 1)
void corr_kernel(const float* __restrict__ in1, const float* __restrict__ in2,
                 float* __restrict__ out)
{
    extern __shared__ float smem[];
    float* s1 = smem;

    const int tid  = threadIdx.x;
    const int team = tid / 192;          // two dy's per block
    const int t192 = tid - team * 192;
    const int y  = blockIdx.x;           // 0..95
    const int zp = blockIdx.y;           // 0..10
    const int b  = blockIdx.z;           // 0..3

    const int  dyIdx     = zp + team * 11;          // 0..21 (21 = idle)
    const bool teamValid = (dyIdx < 21);
    const int  y2        = y + (dyIdx - 10) * 2;
    const bool rowValid  = teamValid && ((unsigned)y2 < 96u);

    float* s2 = smem + S1F + team * S2F;

    // ---- stage in1 row y: smem layout [x][c], row stride RS ----
    {
        const float* g1 = in1 + ((size_t)b * 128 * 96 + y) * 96;   // + ch*4*HW + x
        for (int i = tid; i < 96 * 32; i += 384) {
            int x = i % 96, ch = i / 96;                           // float4 chunk 0..31
            const float* g = g1 + ch * 4 * HW_ + x;
            float4 v = make_float4(g[0], g[HW_], g[2 * HW_], g[3 * HW_]);
            *(float4*)&s1[x * RS + ch * 4] = v;
        }
    }

    // ---- stage in2 row y2 (per team), zero halo rows x in [-20,-1],[96,115] ----
    if (rowValid) {
        for (int i = t192; i < 40 * 32; i += 192) {
            int r = i % 40, ch = i / 40;
            int row = (r < 20) ? r : (96 + r);                     // rows 0..19, 116..135
            *(float4*)&s2[row * RS + ch * 4] = make_float4(0.f, 0.f, 0.f, 0.f);
        }
        const float* g2 = in2 + ((size_t)b * 128 * 96 + y2) * 96;
        for (int i = t192; i < 96 * 32; i += 192) {
            int x = i % 96, ch = i / 96;
            const float* g = g2 + ch * 4 * HW_ + x;
            float4 v = make_float4(g[0], g[HW_], g[2 * HW_], g[3 * HW_]);
            *(float4*)&s2[(x + 20) * RS + ch * 4] = v;
        }
    }
    __syncthreads();

    if (!teamValid) return;

    const int cg = t192 & 3;                 // channel-group lane (8 ch each; shfl-reduced)
    const int xs = t192 >> 2;                // 0..47
    const int x0 = 4 * (xs >> 1) + (xs & 1); // pairs (x0, x0+2) tile 0..95

    const size_t obase = ((size_t)(b * 441 + dyIdx * 21) * 96 + y) * 96;

    if (rowValid) {
        compute_half<0, 11>(s1, s2, x0, cg, out, obase);
        compute_half<11, 10>(s1, s2, x0, cg, out, obase);
    } else {
        // y2 out of range: this dy slab for row y is all zeros
        for (int i = t192; i < 21 * 96; i += 192) {
            int j = i / 96, x = i - j * 96;
            out[obase + (size_t)j * HW_ + x] = 0.f;
        }
    }
}

extern "C" void kernel_launch(void* const* d_in, const int* in_sizes, int n_in,
                              void* d_out, int out_size)
{
    const float* in1 = (const float*)d_in[0];
    const float* in2 = (const float*)d_in[1];
    float* out = (float*)d_out;

    cudaFuncSetAttribute(corr_kernel, cudaFuncAttributeMaxDynamicSharedMemorySize, SMEM_BYTES);

    dim3 grid(96, 11, 4);   // y, dy-pair, batch
    corr_kernel<<<grid, 384, SMEM_BYTES>>>(in1, in2, out);
}

// round 7
// speedup vs baseline: 1.4380x; 1.1595x over previous
#include <cuda_runtime.h>

// FlowNetC correlation, specialized: B=4, C=128, H=W=96, PAD=20, K=1, MD=20, S1=1, S2=2
// out[b, iy*21+ix, y, x] = (1/128) * sum_c in1[b,c,y,x] * in2[b,c,y+dy,x+dx]
//
// R7: channel dim processed in 2 chunks of 64 so smem/block = 63.1KB -> 3 CTAs/SM
// (18 warps/SM vs 12). 192 threads/block, one (y,dy) per block. Rows padded to
// 68 floats: granule index = row + chunk (mod 8) -> conflict-free, affine addrs.

#define HW_ 9216            // 96*96 plane stride in floats
#define RS  68              // padded row stride for 64-ch chunk (floats)
#define S1F (96*RS)         // 6528
#define S2ROWS 136          // x in [-20,115] -> row = x+20
#define S2F (S2ROWS*RS)     // 9248
#define SMEM_FLOATS (S1F + S2F)
#define SMEM_BYTES  (SMEM_FLOATS*4)   // 63,104 B

__global__ __launch_bounds__(192, 3)
void corr_kernel(const float* __restrict__ in1, const float* __restrict__ in2,
                 float* __restrict__ out)
{
    extern __shared__ float smem[];
    float* s1 = smem;
    float* s2 = smem + S1F;

    const int tid   = threadIdx.x;
    const int y     = blockIdx.x;    // 0..95
    const int dyIdx = blockIdx.y;    // 0..20
    const int b     = blockIdx.z;    // 0..3

    const int  y2       = y + (dyIdx - 10) * 2;
    const bool rowValid = ((unsigned)y2 < 96u);

    const size_t obase = ((size_t)(b * 441 + dyIdx * 21) * 96 + y) * 96;

    if (!rowValid) {
        // whole dy slab for this row is zeros (block-uniform; no syncs touched)
        for (int i = tid; i < 21 * 96; i += 192) {
            int j = i / 96, x = i - j * 96;
            out[obase + (size_t)j * HW_ + x] = 0.f;
        }
        return;
    }

    const int cg = tid & 3;                  // channel-group lane (shfl-reduced)
    const int xs = tid >> 2;                 // 0..47
    const int x0 = 4 * (xs >> 1) + (xs & 1); // pairs (x0, x0+2) tile 0..95
    const int x1 = x0 + 2;

    float acc0[21], acc1[21];
    #pragma unroll
    for (int j = 0; j < 21; j++) { acc0[j] = 0.f; acc1[j] = 0.f; }

    #pragma unroll 1
    for (int cc = 0; cc < 2; cc++) {
        // ---- stage in1 row y, channels [cc*64, cc*64+64) : layout [x][c] ----
        const float* g1 = in1 + ((size_t)(b * 128 + cc * 64) * 96 + y) * 96;
        for (int i = tid; i < 96 * 16; i += 192) {
            int x = i % 96, g = i / 96;                      // g = float4 granule 0..15
            const float* p = g1 + g * 4 * HW_ + x;
            *(float4*)&s1[x * RS + g * 4] =
                make_float4(p[0], p[HW_], p[2 * HW_], p[3 * HW_]);
        }
        // ---- zero halo rows (x in [-20,-1] and [96,115]) ----
        for (int i = tid; i < 40 * 16; i += 192) {
            int r = i % 40, g = i / 40;
            int row = (r < 20) ? r : (96 + r);               // rows 0..19, 116..135
            *(float4*)&s2[row * RS + g * 4] = make_float4(0.f, 0.f, 0.f, 0.f);
        }
        // ---- stage in2 row y2, same channel chunk ----
        const float* g2 = in2 + ((size_t)(b * 128 + cc * 64) * 96 + y2) * 96;
        for (int i = tid; i < 96 * 16; i += 192) {
            int x = i % 96, g = i / 96;
            const float* p = g2 + g * 4 * HW_ + x;
            *(float4*)&s2[(x + 20) * RS + g * 4] =
                make_float4(p[0], p[HW_], p[2 * HW_], p[3 * HW_]);
        }
        __syncthreads();

        // ---- compute: lane cg owns granules k*4+cg, k=0..3 (16 ch per chunk) ----
        #pragma unroll 1
        for (int k = 0; k < 4; k++) {
            const int cb = k * 4 + cg;                       // granule 0..15
            const float4 a0 = *(const float4*)&s1[x0 * RS + cb * 4];
            const float4 a1 = *(const float4*)&s1[x1 * RS + cb * 4];
            const float* p2 = &s2[x0 * RS + cb * 4];
            // sliding window: s2 row x0+2t feeds acc0[t] (t<21) and acc1[t-1] (t>0)
            #pragma unroll
            for (int t = 0; t <= 21; t++) {
                const float4 bv = *(const float4*)(p2 + 2 * t * RS);
                if (t < 21) {
                    float s = acc0[t];
                    s = fmaf(a0.x, bv.x, s); s = fmaf(a0.y, bv.y, s);
                    s = fmaf(a0.z, bv.z, s); s = fmaf(a0.w, bv.w, s);
                    acc0[t] = s;
                }
                if (t > 0) {
                    float s = acc1[t - 1];
                    s = fmaf(a1.x, bv.x, s); s = fmaf(a1.y, bv.y, s);
                    s = fmaf(a1.z, bv.z, s); s = fmaf(a1.w, bv.w, s);
                    acc1[t - 1] = s;
                }
            }
        }
        __syncthreads();   // before chunk 1 overwrites smem
    }

    // ---- reduce the 4 channel-group partials (lanes 4*xs + cg) ----
    const float inv = 1.0f / 128.0f;
    #pragma unroll
    for (int j = 0; j < 21; j++) {
        float v0 = acc0[j];
        v0 += __shfl_xor_sync(0xffffffffu, v0, 1);
        v0 += __shfl_xor_sync(0xffffffffu, v0, 2);
        float v1 = acc1[j];
        v1 += __shfl_xor_sync(0xffffffffu, v1, 1);
        v1 += __shfl_xor_sync(0xffffffffu, v1, 2);
        acc0[j] = v0 * inv;
        acc1[j] = v1 * inv;
    }
    if (cg == 0) {
        #pragma unroll
        for (int j = 0; j < 21; j++)
            out[obase + (size_t)j * HW_ + x0] = acc0[j];
    } else if (cg == 1) {
        #pragma unroll
        for (int j = 0; j < 21; j++)
            out[obase + (size_t)j * HW_ + x1] = acc1[j];
    }
}

extern "C" void kernel_launch(void* const* d_in, const int* in_sizes, int n_in,
                              void* d_out, int out_size)
{
    const float* in1 = (const float*)d_in[0];
    const float* in2 = (const float*)d_in[1];
    float* out = (float*)d_out;

    cudaFuncSetAttribute(corr_kernel, cudaFuncAttributeMaxDynamicSharedMemorySize, SMEM_BYTES);

    dim3 grid(96, 21, 4);   // y, dy, batch
    corr_kernel<<<grid, 192, SMEM_BYTES>>>(in1, in2, out);
}